// round 16
// baseline (speedup 1.0000x reference)
#include <cuda_runtime.h>
#include <cuda_bf16.h>

#define NROWS   8192
#define BATCH   8
#define DIM     256
#define NWORDS  (NROWS * NROWS / 32)   // 2,097,152 words = 8 MB

// ---------------- device scratch (static; zero-initialized at module load) --
__device__ __align__(16) unsigned g_bitmap[NWORDS];   // cleared by k_clearbm
__device__ __align__(16) float g_y[BATCH * NROWS * DIM];   // 64 MB tf32(x@W)
__device__ __align__(16) float g_h[BATCH * NROWS * DIM];   // 64 MB A@y

// ---------------- helpers ----------------------------------------------------
__device__ __forceinline__ unsigned f2tf(float f) {
    unsigned u;
    asm("cvt.rna.tf32.f32 %0, %1;" : "=r"(u) : "f"(f));
    return u;
}
__device__ __forceinline__ void mma_tf32(float* d, const unsigned* a,
                                         const unsigned* b) {
    asm volatile(
        "mma.sync.aligned.m16n8k8.row.col.f32.tf32.tf32.f32 "
        "{%0,%1,%2,%3}, {%4,%5,%6,%7}, {%8,%9}, {%0,%1,%2,%3};"
        : "+f"(d[0]), "+f"(d[1]), "+f"(d[2]), "+f"(d[3])
        : "r"(a[0]), "r"(a[1]), "r"(a[2]), "r"(a[3]), "r"(b[0]), "r"(b[1]));
}

// ---------------- kernel 0: clear bitmap (start of every replay) ------------
__global__ void k_clearbm() {
    int i = blockIdx.x * 256 + threadIdx.x;          // 2048*256 = 524288 uint4
    reinterpret_cast<uint4*>(g_bitmap)[i] = make_uint4(0u, 0u, 0u, 0u);
}

// ---------------- kernel 1: scatter edges into bitmap (dedup) ---------------
__global__ void k_scatter(const int* __restrict__ ew, int ne) {
    __shared__ int is32_s;
    const int tid = threadIdx.x;
    if (tid == 0) is32_s = 0;
    __syncthreads();
    if (ew[2 * tid + 1] != 0) is32_s = 1;   // benign race: all writers store 1
    __syncthreads();
    const int is32 = is32_s;

    int i = blockIdx.x * blockDim.x + tid;
    if (i >= ne) return;
    unsigned s, t;
    if (is32) {
        s = (unsigned)ew[2 * i];
        t = (unsigned)ew[2 * i + 1];
    } else {
        const long long* e = (const long long*)ew;
        s = (unsigned)e[2 * i];
        t = (unsigned)e[2 * i + 1];
    }
    unsigned idx = s * (unsigned)NROWS + t;
    atomicOr(&g_bitmap[idx >> 5], 1u << (idx & 31u));
}

// ---------------- kernel 2: y = tf32(x @ W)  (fp32 SGEMM, conflict-free) ----
__global__ void __launch_bounds__(256, 2) k_gemm(const float* __restrict__ X,
                                                 const float* __restrict__ W) {
    __shared__ __align__(16) float As[8][128];   // [k][m]
    __shared__ __align__(16) float Bs[8][128];   // [k][n]

    const int bm  = blockIdx.y * 128;
    const int bn  = blockIdx.x * 128;
    const int tid = threadIdx.x;
    const int ty  = tid >> 4;
    const int tx  = tid & 15;
    const int lrow = tid >> 1;
    const int lc4  = (tid & 1) * 4;
    const int wrow = tid >> 5;
    const int wcol = (tid & 31) * 4;

    float acc[2][2][4][4];
#pragma unroll
    for (int rh = 0; rh < 2; rh++)
#pragma unroll
        for (int ch = 0; ch < 2; ch++)
#pragma unroll
            for (int i = 0; i < 4; i++)
#pragma unroll
                for (int j = 0; j < 4; j++) acc[rh][ch][i][j] = 0.f;

    for (int kt = 0; kt < DIM; kt += 8) {
        float4 xv = *reinterpret_cast<const float4*>(
            &X[(size_t)(bm + lrow) * DIM + kt + lc4]);
        As[lc4 + 0][lrow] = xv.x;
        As[lc4 + 1][lrow] = xv.y;
        As[lc4 + 2][lrow] = xv.z;
        As[lc4 + 3][lrow] = xv.w;
        *reinterpret_cast<float4*>(&Bs[wrow][wcol]) =
            *reinterpret_cast<const float4*>(&W[(size_t)(kt + wrow) * DIM + bn + wcol]);
        __syncthreads();

#pragma unroll
        for (int k = 0; k < 8; k++) {
            float a[2][4], b[2][4];
            *reinterpret_cast<float4*>(&a[0][0]) =
                *reinterpret_cast<const float4*>(&As[k][ty * 4]);
            *reinterpret_cast<float4*>(&a[1][0]) =
                *reinterpret_cast<const float4*>(&As[k][64 + ty * 4]);
            *reinterpret_cast<float4*>(&b[0][0]) =
                *reinterpret_cast<const float4*>(&Bs[k][tx * 4]);
            *reinterpret_cast<float4*>(&b[1][0]) =
                *reinterpret_cast<const float4*>(&Bs[k][64 + tx * 4]);
#pragma unroll
            for (int rh = 0; rh < 2; rh++)
#pragma unroll
                for (int ch = 0; ch < 2; ch++)
#pragma unroll
                    for (int i = 0; i < 4; i++)
#pragma unroll
                        for (int j = 0; j < 4; j++)
                            acc[rh][ch][i][j] =
                                fmaf(a[rh][i], b[ch][j], acc[rh][ch][i][j]);
        }
        __syncthreads();
    }

#pragma unroll
    for (int rh = 0; rh < 2; rh++)
#pragma unroll
        for (int i = 0; i < 4; i++) {
            const int row = bm + rh * 64 + ty * 4 + i;
#pragma unroll
            for (int ch = 0; ch < 2; ch++) {
                float o[4];
#pragma unroll
                for (int j = 0; j < 4; j++)
                    o[j] = __uint_as_float(f2tf(acc[rh][ch][i][j]));  // pre-round
                *reinterpret_cast<float4*>(
                    &g_y[(size_t)row * DIM + bn + ch * 64 + tx * 4]) =
                    *reinterpret_cast<float4*>(&o[0]);
            }
        }
}

// ---------------- kernel 3: H = A @ Y_b  (bitmap A, BK=64, skip+reuse) ------
// grid (16, 64): blockIdx.x = b*2 + n-half; BM=128, BN=128, BK=64; 256 thr.
// 8 warps as 2(m) x 4(n): warp tile 64m x 32n = 4 x 4 m16n8k8 atoms.
// BK=64 halves barrier count and pays the per-phase LDG latency once for 2x
// the compute. Zero-chunk skip (ballot, warp-uniform) + bf reuse preserved.
#define B_ST 132

__global__ void __launch_bounds__(256, 2) k_mma() {
    __shared__ __align__(16) float    Bs[64 * B_ST];   // Y tile [k][n] 64x128
    __shared__ unsigned bm_s[256];                     // 2 words per m-row

    const int b    = blockIdx.x >> 1;
    const int nt   = (blockIdx.x & 1) * 128;     // n-half offset within DIM
    const int mt   = blockIdx.y * 128;
    const int tid  = threadIdx.x;
    const int lane = tid & 31;
    const int warp = tid >> 5;
    const int wm   = warp >> 2;          // 0..1
    const int wn   = warp & 3;           // 0..3
    const int lr   = lane >> 2;          // 0..7
    const int lc   = lane & 3;           // 0..3

    const float* Yb = g_y + (size_t)b * NROWS * DIM + nt;
    const int br = tid >> 2;             // Y tile row 0..63
    const int bq = tid & 3;              // Y float4 phase 0..3

    float acc[4][4][4];
#pragma unroll
    for (int ma = 0; ma < 4; ma++)
#pragma unroll
        for (int na = 0; na < 4; na++)
#pragma unroll
            for (int r = 0; r < 4; r++) acc[ma][na][r] = 0.f;

    for (int kt = 0; kt < NROWS; kt += 64) {
        __syncthreads();
        // bitmap: 2 words (64 k-bits) per m-row; uint2-aligned (kt/32 even)
        if (tid < 128) {
            uint2 w = *reinterpret_cast<const uint2*>(
                &g_bitmap[(size_t)(mt + tid) * (NROWS / 32) + (kt >> 5)]);
            bm_s[tid]       = w.x;       // k bits [kt, kt+32)
            bm_s[128 + tid] = w.y;       // k bits [kt+32, kt+64)
        }
        // Y tile 64 x 128: 8 float4 per thread (deep MLP, one latency pay)
        const float4* Yrow = reinterpret_cast<const float4*>(
            Yb + (size_t)(kt + br) * DIM);
        float* bdst = Bs + br * B_ST;
#pragma unroll
        for (int j = 0; j < 8; j++) {
            float4 v = __ldg(&Yrow[bq + 4 * j]);
            *reinterpret_cast<float4*>(bdst + (bq + 4 * j) * 4) = v;
        }
        __syncthreads();

#pragma unroll
        for (int half = 0; half < 2; half++) {
            // nibble-expanded bit words per ma for this 32-k half
            unsigned xw[4][2];
#pragma unroll
            for (int ma = 0; ma < 4; ma++) {
                const int m0 = wm * 64 + ma * 16 + lr;
                xw[ma][0] = (bm_s[half * 128 + m0]     >> lc) & 0x11111111u;
                xw[ma][1] = (bm_s[half * 128 + m0 + 8] >> lc) & 0x11111111u;
            }
#pragma unroll
            for (int ks = 0; ks < 4; ks++) {
                const int k0 = half * 32 + ks * 8;
                unsigned tA[4], tB[4];
                unsigned actm = 0;
#pragma unroll
                for (int ma = 0; ma < 4; ma++) {
                    tA[ma] = (xw[ma][0] >> (8 * ks)) & 0xFFu;
                    tB[ma] = (xw[ma][1] >> (8 * ks)) & 0xFFu;
                    if (__ballot_sync(0xffffffffu, (tA[ma] | tB[ma]) != 0u))
                        actm |= 1u << ma;
                }
                if (actm == 0u) continue;   // whole ks empty: skip bf loads

                unsigned a[4][4];
#pragma unroll
                for (int ma = 0; ma < 4; ma++) {
                    if (!(actm & (1u << ma))) continue;
                    a[ma][0] = (tA[ma] & 0xFu) * 0x3F800000u;
                    a[ma][1] = (tB[ma] & 0xFu) * 0x3F800000u;
                    a[ma][2] = (tA[ma] >> 4)   * 0x3F800000u;
                    a[ma][3] = (tB[ma] >> 4)   * 0x3F800000u;
                }
#pragma unroll
                for (int na = 0; na < 4; na++) {
                    unsigned bf[2];
                    const int n0 = wn * 32 + na * 8 + lr;
                    bf[0] = __float_as_uint(Bs[(k0 + lc)     * B_ST + n0]);
                    bf[1] = __float_as_uint(Bs[(k0 + lc + 4) * B_ST + n0]);
#pragma unroll
                    for (int ma = 0; ma < 4; ma++)
                        if (actm & (1u << ma)) mma_tf32(acc[ma][na], a[ma], bf);
                }
            }
        }
    }

    // epilogue: write H[b][m][d]
    float* Hb = g_h + (size_t)b * NROWS * DIM;
#pragma unroll
    for (int ma = 0; ma < 4; ma++)
#pragma unroll
        for (int na = 0; na < 4; na++) {
            const int r0 = mt + wm * 64 + ma * 16 + lr;
            const int c0 = nt + wn * 32 + na * 8 + lc * 2;
            *reinterpret_cast<float2*>(&Hb[(size_t)r0 * DIM + c0]) =
                make_float2(acc[ma][na][0], acc[ma][na][1]);
            *reinterpret_cast<float2*>(&Hb[(size_t)(r0 + 8) * DIM + c0]) =
                make_float2(acc[ma][na][2], acc[ma][na][3]);
        }
}

// ---------------- kernel 4: LeakyReLU + LayerNorm ---------------------------
__global__ void __launch_bounds__(64) k_ln(const float* __restrict__ gamma,
                                           const float* __restrict__ beta,
                                           float* __restrict__ out) {
    const int row  = blockIdx.x;
    const int tid  = threadIdx.x;    // 0..63
    const int lane = tid & 31, warp = tid >> 5;
    __shared__ float rs[2], rq[2];

    float4 v = __ldg(&reinterpret_cast<const float4*>(g_h)[(size_t)row * 64 + tid]);
    v.x = v.x >= 0.f ? v.x : 0.1f * v.x;
    v.y = v.y >= 0.f ? v.y : 0.1f * v.y;
    v.z = v.z >= 0.f ? v.z : 0.1f * v.z;
    v.w = v.w >= 0.f ? v.w : 0.1f * v.w;

    float s = (v.x + v.y) + (v.z + v.w);
    float q = (v.x * v.x + v.y * v.y) + (v.z * v.z + v.w * v.w);
#pragma unroll
    for (int off = 16; off > 0; off >>= 1) {
        s += __shfl_down_sync(0xffffffffu, s, off);
        q += __shfl_down_sync(0xffffffffu, q, off);
    }
    if (lane == 0) { rs[warp] = s; rq[warp] = q; }
    __syncthreads();
    const float st = rs[0] + rs[1];
    const float qt = rq[0] + rq[1];

    const float mean = st * (1.f / 256.f);
    const float var  = qt * (1.f / 256.f) - mean * mean;
    const float inv  = rsqrtf(var + 1e-5f);

    const float4 g4  = __ldg(&reinterpret_cast<const float4*>(gamma)[tid]);
    const float4 be4 = __ldg(&reinterpret_cast<const float4*>(beta)[tid]);
    float4 o;
    o.x = g4.x * (v.x - mean) * inv + be4.x;
    o.y = g4.y * (v.y - mean) * inv + be4.y;
    o.z = g4.z * (v.z - mean) * inv + be4.z;
    o.w = g4.w * (v.w - mean) * inv + be4.w;
    reinterpret_cast<float4*>(out)[(size_t)row * 64 + tid] = o;
}

// ---------------- launcher ---------------------------------------------------
extern "C" void kernel_launch(void* const* d_in, const int* in_sizes, int n_in,
                              void* d_out, int out_size) {
    const float* x     = (const float*)d_in[0];   // (8, 8192, 256) f32
    const float* W     = (const float*)d_in[1];   // (256, 256) f32
    const float* gamma = (const float*)d_in[2];   // (256,) f32
    const float* beta  = (const float*)d_in[3];   // (256,) f32
    const int*   edges = (const int*)d_in[4];     // (262144, 2) int32 or int64
    const int ne = in_sizes[4] / 2;
    float* out = (float*)d_out;

    // 5 launches; ncu's capture slot (4th) = k_mma.
    k_clearbm<<<2048, 256>>>();                        // bitmap zero each replay
    k_scatter<<<(ne + 255) / 256, 256>>>(edges, ne);
    dim3 ggrid(DIM / 128, (BATCH * NROWS) / 128);      // (2, 512)
    k_gemm<<<ggrid, 256>>>(x, W);
    dim3 mgrid(BATCH * 2, NROWS / 128);                // (16, 64)
    k_mma<<<mgrid, 256>>>();
    k_ln<<<BATCH * NROWS, 64>>>(gamma, beta, out);
}

// round 17
// speedup vs baseline: 1.6732x; 1.6732x over previous
#include <cuda_runtime.h>
#include <cuda_bf16.h>

#define NROWS   8192
#define BATCH   8
#define DIM     256
#define NWORDS  (NROWS * NROWS / 32)   // 2,097,152 words = 8 MB

// ---------------- device scratch (static; zero-initialized at module load) --
__device__ __align__(16) unsigned g_bitmap[NWORDS];   // cleared by k_clearbm
__device__ __align__(16) float g_y[BATCH * NROWS * DIM];   // 64 MB tf32(x@W)
__device__ __align__(16) float g_h[BATCH * NROWS * DIM];   // 64 MB A@y

// ---------------- helpers ----------------------------------------------------
__device__ __forceinline__ unsigned f2tf(float f) {
    unsigned u;
    asm("cvt.rna.tf32.f32 %0, %1;" : "=r"(u) : "f"(f));
    return u;
}
__device__ __forceinline__ void mma_tf32(float* d, const unsigned* a,
                                         const unsigned* b) {
    asm volatile(
        "mma.sync.aligned.m16n8k8.row.col.f32.tf32.tf32.f32 "
        "{%0,%1,%2,%3}, {%4,%5,%6,%7}, {%8,%9}, {%0,%1,%2,%3};"
        : "+f"(d[0]), "+f"(d[1]), "+f"(d[2]), "+f"(d[3])
        : "r"(a[0]), "r"(a[1]), "r"(a[2]), "r"(a[3]), "r"(b[0]), "r"(b[1]));
}
__device__ __forceinline__ void cp_async16(void* smem_dst, const void* gsrc) {
    unsigned saddr = (unsigned)__cvta_generic_to_shared(smem_dst);
    asm volatile("cp.async.cg.shared.global [%0], [%1], 16;"
                 :: "r"(saddr), "l"(gsrc));
}
__device__ __forceinline__ void cp_async4(void* smem_dst, const void* gsrc) {
    unsigned saddr = (unsigned)__cvta_generic_to_shared(smem_dst);
    asm volatile("cp.async.ca.shared.global [%0], [%1], 4;"
                 :: "r"(saddr), "l"(gsrc));
}
__device__ __forceinline__ void cp_commit() {
    asm volatile("cp.async.commit_group;");
}
template <int N>
__device__ __forceinline__ void cp_wait() {
    asm volatile("cp.async.wait_group %0;" :: "n"(N));
}

// ---------------- kernel 0: clear bitmap (start of every replay) ------------
__global__ void k_clearbm() {
    int i = blockIdx.x * 256 + threadIdx.x;          // 2048*256 = 524288 uint4
    reinterpret_cast<uint4*>(g_bitmap)[i] = make_uint4(0u, 0u, 0u, 0u);
}

// ---------------- kernel 1: scatter edges into bitmap (dedup) ---------------
__global__ void k_scatter(const int* __restrict__ ew, int ne) {
    __shared__ int is32_s;
    const int tid = threadIdx.x;
    if (tid == 0) is32_s = 0;
    __syncthreads();
    if (ew[2 * tid + 1] != 0) is32_s = 1;   // benign race: all writers store 1
    __syncthreads();
    const int is32 = is32_s;

    int i = blockIdx.x * blockDim.x + tid;
    if (i >= ne) return;
    unsigned s, t;
    if (is32) {
        s = (unsigned)ew[2 * i];
        t = (unsigned)ew[2 * i + 1];
    } else {
        const long long* e = (const long long*)ew;
        s = (unsigned)e[2 * i];
        t = (unsigned)e[2 * i + 1];
    }
    unsigned idx = s * (unsigned)NROWS + t;
    atomicOr(&g_bitmap[idx >> 5], 1u << (idx & 31u));
}

// ---------------- kernel 2: y = tf32(x @ W)  (fp32 SGEMM, conflict-free) ----
__global__ void __launch_bounds__(256, 2) k_gemm(const float* __restrict__ X,
                                                 const float* __restrict__ W) {
    __shared__ __align__(16) float As[8][128];   // [k][m]
    __shared__ __align__(16) float Bs[8][128];   // [k][n]

    const int bm  = blockIdx.y * 128;
    const int bn  = blockIdx.x * 128;
    const int tid = threadIdx.x;
    const int ty  = tid >> 4;
    const int tx  = tid & 15;
    const int lrow = tid >> 1;
    const int lc4  = (tid & 1) * 4;
    const int wrow = tid >> 5;
    const int wcol = (tid & 31) * 4;

    float acc[2][2][4][4];
#pragma unroll
    for (int rh = 0; rh < 2; rh++)
#pragma unroll
        for (int ch = 0; ch < 2; ch++)
#pragma unroll
            for (int i = 0; i < 4; i++)
#pragma unroll
                for (int j = 0; j < 4; j++) acc[rh][ch][i][j] = 0.f;

    for (int kt = 0; kt < DIM; kt += 8) {
        float4 xv = *reinterpret_cast<const float4*>(
            &X[(size_t)(bm + lrow) * DIM + kt + lc4]);
        As[lc4 + 0][lrow] = xv.x;
        As[lc4 + 1][lrow] = xv.y;
        As[lc4 + 2][lrow] = xv.z;
        As[lc4 + 3][lrow] = xv.w;
        *reinterpret_cast<float4*>(&Bs[wrow][wcol]) =
            *reinterpret_cast<const float4*>(&W[(size_t)(kt + wrow) * DIM + bn + wcol]);
        __syncthreads();

#pragma unroll
        for (int k = 0; k < 8; k++) {
            float a[2][4], b[2][4];
            *reinterpret_cast<float4*>(&a[0][0]) =
                *reinterpret_cast<const float4*>(&As[k][ty * 4]);
            *reinterpret_cast<float4*>(&a[1][0]) =
                *reinterpret_cast<const float4*>(&As[k][64 + ty * 4]);
            *reinterpret_cast<float4*>(&b[0][0]) =
                *reinterpret_cast<const float4*>(&Bs[k][tx * 4]);
            *reinterpret_cast<float4*>(&b[1][0]) =
                *reinterpret_cast<const float4*>(&Bs[k][64 + tx * 4]);
#pragma unroll
            for (int rh = 0; rh < 2; rh++)
#pragma unroll
                for (int ch = 0; ch < 2; ch++)
#pragma unroll
                    for (int i = 0; i < 4; i++)
#pragma unroll
                        for (int j = 0; j < 4; j++)
                            acc[rh][ch][i][j] =
                                fmaf(a[rh][i], b[ch][j], acc[rh][ch][i][j]);
        }
        __syncthreads();
    }

#pragma unroll
    for (int rh = 0; rh < 2; rh++)
#pragma unroll
        for (int i = 0; i < 4; i++) {
            const int row = bm + rh * 64 + ty * 4 + i;
#pragma unroll
            for (int ch = 0; ch < 2; ch++) {
                float o[4];
#pragma unroll
                for (int j = 0; j < 4; j++)
                    o[j] = __uint_as_float(f2tf(acc[rh][ch][i][j]));  // pre-round
                *reinterpret_cast<float4*>(
                    &g_y[(size_t)row * DIM + bn + ch * 64 + tx * 4]) =
                    *reinterpret_cast<float4*>(&o[0]);
            }
        }
}

// ---------------- kernel 3: H = A @ Y_b  (cp.async 2-stage, 1 bar/tile) -----
// grid (16, 64): blockIdx.x = b*2 + n-half; BM=128, BN=128, BK=32; 256 thr.
// 8 warps as 2(m) x 4(n): warp tile 64m x 32n = 4 x 4 m16n8k8 atoms.
// Pipeline per tile: wait(t) -> ONE syncthreads -> cp.async issue(t+1) ->
// compute(t). The LDG latency of tile t+1 is hidden behind compute(t).
// Zero-chunk skip (ballot) + bf reuse preserved from R15.
#define B_ST 132

__global__ void __launch_bounds__(256, 2) k_mma() {
    __shared__ __align__(16) float    Bs[2][32 * B_ST];  // Y tiles, 2 stages
    __shared__ unsigned bm_s[2][128];                    // bitmap words, 2 stages

    const int b    = blockIdx.x >> 1;
    const int nt   = (blockIdx.x & 1) * 128;     // n-half offset within DIM
    const int mt   = blockIdx.y * 128;
    const int tid  = threadIdx.x;
    const int lane = tid & 31;
    const int warp = tid >> 5;
    const int wm   = warp >> 2;          // 0..1
    const int wn   = warp & 3;           // 0..3
    const int lr   = lane >> 2;          // 0..7
    const int lc   = lane & 3;           // 0..3

    const float* Yb = g_y + (size_t)b * NROWS * DIM + nt;
    const int br = tid >> 3;             // Y tile row 0..31
    const int bq = tid & 7;              // Y float4 lane 0..7

    float acc[4][4][4];
#pragma unroll
    for (int ma = 0; ma < 4; ma++)
#pragma unroll
        for (int na = 0; na < 4; na++)
#pragma unroll
            for (int r = 0; r < 4; r++) acc[ma][na][r] = 0.f;

    auto issue = [&](int kt, int stg) {
        if (tid < 128)
            cp_async4(&bm_s[stg][tid],
                      &g_bitmap[(size_t)(mt + tid) * (NROWS / 32) + (kt >> 5)]);
        const float* ysrc = Yb + (size_t)(kt + br) * DIM;
        float* bdst = Bs[stg] + br * B_ST;
#pragma unroll
        for (int j = 0; j < 4; j++)
            cp_async16(bdst + (bq + 8 * j) * 4, ysrc + (bq + 8 * j) * 4);
    };

    issue(0, 0);
    cp_commit();

    const int NKT = NROWS / 32;          // 256
    for (int it = 0; it < NKT; it++) {
        cp_wait<0>();        // tile it landed (only pending group)
        __syncthreads();     // all warps: tile it visible AND compute(it-1)
                             // done -> stage (it+1)&1 is free to overwrite
        if (it + 1 < NKT) {
            issue(it + 1 == NKT ? 0 : (it + 1) * 32, (it + 1) & 1);
            cp_commit();     // flies during compute(it)
        }
        const int stg = it & 1;

        // nibble-expanded bit words per ma (bit lc+4t -> nibble t)
        unsigned xw[4][2];
#pragma unroll
        for (int ma = 0; ma < 4; ma++) {
            const int m0 = wm * 64 + ma * 16 + lr;
            xw[ma][0] = (bm_s[stg][m0]     >> lc) & 0x11111111u;
            xw[ma][1] = (bm_s[stg][m0 + 8] >> lc) & 0x11111111u;
        }

#pragma unroll
        for (int ks = 0; ks < 4; ks++) {
            const int k0 = ks * 8;
            unsigned tA[4], tB[4];
            unsigned actm = 0;
#pragma unroll
            for (int ma = 0; ma < 4; ma++) {
                tA[ma] = (xw[ma][0] >> (8 * ks)) & 0xFFu;
                tB[ma] = (xw[ma][1] >> (8 * ks)) & 0xFFu;
                if (__ballot_sync(0xffffffffu, (tA[ma] | tB[ma]) != 0u))
                    actm |= 1u << ma;
            }
            if (actm == 0u) continue;   // whole ks empty: skip bf loads too

            unsigned a[4][4];
#pragma unroll
            for (int ma = 0; ma < 4; ma++) {
                if (!(actm & (1u << ma))) continue;
                a[ma][0] = (tA[ma] & 0xFu) * 0x3F800000u;
                a[ma][1] = (tB[ma] & 0xFu) * 0x3F800000u;
                a[ma][2] = (tA[ma] >> 4)   * 0x3F800000u;
                a[ma][3] = (tB[ma] >> 4)   * 0x3F800000u;
            }
#pragma unroll
            for (int na = 0; na < 4; na++) {
                unsigned bf[2];
                const int n0 = wn * 32 + na * 8 + lr;
                bf[0] = __float_as_uint(Bs[stg][(k0 + lc)     * B_ST + n0]);
                bf[1] = __float_as_uint(Bs[stg][(k0 + lc + 4) * B_ST + n0]);
#pragma unroll
                for (int ma = 0; ma < 4; ma++)
                    if (actm & (1u << ma)) mma_tf32(acc[ma][na], a[ma], bf);
            }
        }
    }

    // epilogue: write H[b][m][d]
    float* Hb = g_h + (size_t)b * NROWS * DIM;
#pragma unroll
    for (int ma = 0; ma < 4; ma++)
#pragma unroll
        for (int na = 0; na < 4; na++) {
            const int r0 = mt + wm * 64 + ma * 16 + lr;
            const int c0 = nt + wn * 32 + na * 8 + lc * 2;
            *reinterpret_cast<float2*>(&Hb[(size_t)r0 * DIM + c0]) =
                make_float2(acc[ma][na][0], acc[ma][na][1]);
            *reinterpret_cast<float2*>(&Hb[(size_t)(r0 + 8) * DIM + c0]) =
                make_float2(acc[ma][na][2], acc[ma][na][3]);
        }
}

// ---------------- kernel 4: LeakyReLU + LayerNorm ---------------------------
__global__ void __launch_bounds__(64) k_ln(const float* __restrict__ gamma,
                                           const float* __restrict__ beta,
                                           float* __restrict__ out) {
    const int row  = blockIdx.x;
    const int tid  = threadIdx.x;    // 0..63
    const int lane = tid & 31, warp = tid >> 5;
    __shared__ float rs[2], rq[2];

    float4 v = __ldg(&reinterpret_cast<const float4*>(g_h)[(size_t)row * 64 + tid]);
    v.x = v.x >= 0.f ? v.x : 0.1f * v.x;
    v.y = v.y >= 0.f ? v.y : 0.1f * v.y;
    v.z = v.z >= 0.f ? v.z : 0.1f * v.z;
    v.w = v.w >= 0.f ? v.w : 0.1f * v.w;

    float s = (v.x + v.y) + (v.z + v.w);
    float q = (v.x * v.x + v.y * v.y) + (v.z * v.z + v.w * v.w);
#pragma unroll
    for (int off = 16; off > 0; off >>= 1) {
        s += __shfl_down_sync(0xffffffffu, s, off);
        q += __shfl_down_sync(0xffffffffu, q, off);
    }
    if (lane == 0) { rs[warp] = s; rq[warp] = q; }
    __syncthreads();
    const float st = rs[0] + rs[1];
    const float qt = rq[0] + rq[1];

    const float mean = st * (1.f / 256.f);
    const float var  = qt * (1.f / 256.f) - mean * mean;
    const float inv  = rsqrtf(var + 1e-5f);

    const float4 g4  = __ldg(&reinterpret_cast<const float4*>(gamma)[tid]);
    const float4 be4 = __ldg(&reinterpret_cast<const float4*>(beta)[tid]);
    float4 o;
    o.x = g4.x * (v.x - mean) * inv + be4.x;
    o.y = g4.y * (v.y - mean) * inv + be4.y;
    o.z = g4.z * (v.z - mean) * inv + be4.z;
    o.w = g4.w * (v.w - mean) * inv + be4.w;
    reinterpret_cast<float4*>(out)[(size_t)row * 64 + tid] = o;
}

// ---------------- launcher ---------------------------------------------------
extern "C" void kernel_launch(void* const* d_in, const int* in_sizes, int n_in,
                              void* d_out, int out_size) {
    const float* x     = (const float*)d_in[0];   // (8, 8192, 256) f32
    const float* W     = (const float*)d_in[1];   // (256, 256) f32
    const float* gamma = (const float*)d_in[2];   // (256,) f32
    const float* beta  = (const float*)d_in[3];   // (256,) f32
    const int*   edges = (const int*)d_in[4];     // (262144, 2) int32 or int64
    const int ne = in_sizes[4] / 2;
    float* out = (float*)d_out;

    // 5 launches; ncu's capture slot (4th) = k_mma.
    k_clearbm<<<2048, 256>>>();                        // bitmap zero each replay
    k_scatter<<<(ne + 255) / 256, 256>>>(edges, ne);
    dim3 ggrid(DIM / 128, (BATCH * NROWS) / 128);      // (2, 512)
    k_gemm<<<ggrid, 256>>>(x, W);
    dim3 mgrid(BATCH * 2, NROWS / 128);                // (16, 64)
    k_mma<<<mgrid, 256>>>();
    k_ln<<<BATCH * NROWS, 64>>>(gamma, beta, out);
}